// round 14
// baseline (speedup 1.0000x reference)
#include <cuda_runtime.h>
#include <cstdint>

// LoRA linear via rank-16 factor:
//   t   = x @ A^T   : [16384,4096] @ [4096,16] -> [16384,16]   (stage 1, split-K x2)
//   out = t @ B^T   : [16384,16]   @ [16,4096] -> [16384,4096] (stage 2, R6 form)

#define D 4096
#define R 16
#define ROWS_TOTAL 16384
#define KC 32
#define KHALF 2048
#define NCHH (KHALF / KC)   // 64 chunks per k-half
#define ADS 18              // ad row stride in u64
#define AD_STAGE (16 * ADS)

typedef unsigned long long u64;

// 8 k-partials: [khalf*4 + kq][row][r]  (8 MB, fully overwritten each call)
__device__ float g_tp[8][ROWS_TOTAL * R];

__device__ __forceinline__ u64 fma2(u64 a, u64 b, u64 c) {
    u64 d; asm("fma.rn.f32x2 %0,%1,%2,%3;" : "=l"(d) : "l"(a), "l"(b), "l"(c)); return d;
}
__device__ __forceinline__ u64 pack2(float lo, float hi) {
    u64 d; asm("mov.b64 %0,{%1,%2};" : "=l"(d) : "f"(lo), "f"(hi)); return d;
}
__device__ __forceinline__ float hsum2(u64 v) {
    float lo, hi; asm("mov.b64 {%0,%1},%2;" : "=f"(lo), "=f"(hi) : "l"(v)); return lo + hi;
}
__device__ __forceinline__ void cp16(uint32_t d, const void* s) {
    asm volatile("cp.async.cg.shared.global [%0],[%1],16;" :: "r"(d), "l"(s));
}
__device__ __forceinline__ void cpcommit() { asm volatile("cp.async.commit_group;"); }
__device__ __forceinline__ void cpwait2()  { asm volatile("cp.async.wait_group 2;"); }

// ---------------- Stage 1: t-partials = x @ A^T (split-K) ----------------
// Grid (256 row-blocks, 2 k-halves), 256 thr / 8 warps, 64 rows, 3 CTAs/SM.
// Warp w: rows (w&1)*32 + lane, k-quarter kq = w>>1 (8 k per chunk).
// acc = 1 row x 16 r in f32x2 over (k-even,k-odd) = 16 u64 (32 regs).
// A reads remain pure warp-broadcasts (kq is warp-uniform).
// 4-stage cp.async ring, ONE __syncthreads per chunk (R6 discipline).
// Epilogue: straight STG of this (row, kq) partial -> g_tp; no reduction.
__global__ void __launch_bounds__(256, 3)
lora_stage1(const float* __restrict__ x, const float* __restrict__ A)
{
    __shared__ __align__(16) unsigned char sm[42 * 1024];
    float* xs = (float*)sm;                  // [4][64 rows][32 k]  32 KB
    u64*   ad = (u64*)(sm + 32768);          // [4][16][ADS]        9.2 KB

    const int tid  = threadIdx.x;
    const int w    = tid >> 5;
    const int lane = tid & 31;
    const long rowBase = (long)blockIdx.x * 64;
    const int  kbase   = blockIdx.y * KHALF;

    // x cp.async role: row = tid>>2, seg = tid&3 (8 floats = 2 slots)
    const int trow = tid >> 2, tseg = tid & 3;
    const int tph0 = (2 * tseg)     ^ (trow & 7);
    const int tph1 = (2 * tseg + 1) ^ (trow & 7);
    const float* xsrc = x + (rowBase + trow) * D + kbase;
    const uint32_t xs_sh = (uint32_t)__cvta_generic_to_shared(sm);

    // A role: r = tid>>4, kp = tid&15 (coalesced float2 per r-row)
    const int ar = tid >> 4, akp = tid & 15;
    const float* asrc = A + (long)ar * D + kbase + 2 * akp;

    // compute role: row, k-quarter
    const int row = (w & 1) * 32 + lane;
    const int kq  = w >> 1;
    const int p0  = ((2 * kq)     ^ (row & 7)) * 4;
    const int p1  = ((2 * kq + 1) ^ (row & 7)) * 4;
    const float* xrd = xs + row * 32;

    u64 acc[16];
    #pragma unroll
    for (int r = 0; r < 16; ++r) acc[r] = 0ULL;

    // ---- prologue: x chunks 0..2 in flight, A(0..1) staged, A(2) in regs ----
    #pragma unroll
    for (int cc = 0; cc < 3; ++cc) {
        const float* xp = xsrc + cc * KC + tseg * 8;
        cp16(xs_sh + (uint32_t)(cc * 2048 + trow * 32 + tph0 * 4) * 4u, xp);
        cp16(xs_sh + (uint32_t)(cc * 2048 + trow * 32 + tph1 * 4) * 4u, xp + 4);
        cpcommit();
    }
    {
        float2 t0 = *(const float2*)(asrc);
        float2 t1 = *(const float2*)(asrc + KC);
        ad[0 * AD_STAGE + akp * ADS + ar] = pack2(t0.x, t0.y);
        ad[1 * AD_STAGE + akp * ADS + ar] = pack2(t1.x, t1.y);
    }
    float2 apf = *(const float2*)(asrc + 2 * KC);

    #pragma unroll 4
    for (int c = 0; c < NCHH; ++c) {
        const int s = c & 3;
        cpwait2();           // chunk c landed (this thread's groups)
        __syncthreads();     // visible to all + compute(c-1) done

        if (c + 3 < NCHH) {
            const float* xp = xsrc + (c + 3) * KC + tseg * 8;
            const uint32_t base = (uint32_t)(((c + 3) & 3) * 2048 + trow * 32);
            cp16(xs_sh + (base + tph0 * 4) * 4u, xp);
            cp16(xs_sh + (base + tph1 * 4) * 4u, xp + 4);
        }
        cpcommit();          // always: group count tracks chunk count

        if (c + 2 < NCHH)
            ad[((c + 2) & 3) * AD_STAGE + akp * ADS + ar] = pack2(apf.x, apf.y);
        if (c + 3 < NCHH)
            apf = *(const float2*)(asrc + (c + 3) * KC);

        // ---- compute chunk c: k = kq*8 .. kq*8+7 (k-pairs 4kq..4kq+3) ----
        const float* xb = xrd + s * 2048;
        ulonglong2 xa = *(const ulonglong2*)(xb + p0);   // kp 4kq, 4kq+1
        ulonglong2 xc = *(const ulonglong2*)(xb + p1);   // kp 4kq+2, 4kq+3
        u64 xk[4] = { xa.x, xa.y, xc.x, xc.y };

        const u64* adc = ad + s * AD_STAGE;
        #pragma unroll
        for (int j = 0; j < 4; ++j) {
            const u64 xv = xk[j];
            const u64* adk = adc + (4 * kq + j) * ADS;
            #pragma unroll
            for (int rr = 0; rr < 8; ++rr) {
                ulonglong2 av = *(const ulonglong2*)(adk + 2 * rr);  // broadcast
                acc[2 * rr]     = fma2(xv, av.x, acc[2 * rr]);
                acc[2 * rr + 1] = fma2(xv, av.y, acc[2 * rr + 1]);
            }
        }
    }

    // ---- epilogue: write this (row, kq) partial directly ----
    {
        float* gp = g_tp[blockIdx.y * 4 + kq] + (rowBase + row) * R;
        #pragma unroll
        for (int q = 0; q < 4; ++q)
            *(float4*)(gp + 4 * q) = make_float4(
                hsum2(acc[4 * q]),     hsum2(acc[4 * q + 1]),
                hsum2(acc[4 * q + 2]), hsum2(acc[4 * q + 3]));
    }
}

// ---------------- Stage 2: out = t @ B^T ---------------- (R6 form + partial sum)
__global__ void __launch_bounds__(256, 2)
lora_stage2(const float* __restrict__ B, float* __restrict__ out)
{
    __shared__ float ts[128 * R];   // 8 KB

    const int tid = threadIdx.x;
    const long rowBase = (long)blockIdx.y * 128;
    const int ob = blockIdx.x * 1024 + tid * 4;

    // t tile = sum of 8 k-partials (L2-resident)
    {
        const long off = rowBase * R + tid * 8;
        float4 s0 = make_float4(0.f, 0.f, 0.f, 0.f);
        float4 s1 = make_float4(0.f, 0.f, 0.f, 0.f);
        #pragma unroll
        for (int p = 0; p < 8; ++p) {
            float4 a = *(const float4*)(g_tp[p] + off);
            float4 b = *(const float4*)(g_tp[p] + off + 4);
            s0.x += a.x; s0.y += a.y; s0.z += a.z; s0.w += a.w;
            s1.x += b.x; s1.y += b.y; s1.z += b.z; s1.w += b.w;
        }
        *(float4*)(ts + tid * 8)     = s0;
        *(float4*)(ts + tid * 8 + 4) = s1;
    }

    u64 bb[4][8];
    #pragma unroll
    for (int j = 0; j < 4; ++j) {
        const float* bp = B + (long)(ob + j) * R;
        ulonglong2 v0 = *(const ulonglong2*)(bp);
        ulonglong2 v1 = *(const ulonglong2*)(bp + 4);
        ulonglong2 v2 = *(const ulonglong2*)(bp + 8);
        ulonglong2 v3 = *(const ulonglong2*)(bp + 12);
        bb[j][0] = v0.x; bb[j][1] = v0.y;
        bb[j][2] = v1.x; bb[j][3] = v1.y;
        bb[j][4] = v2.x; bb[j][5] = v2.y;
        bb[j][6] = v3.x; bb[j][7] = v3.y;
    }
    __syncthreads();

    for (int row = 0; row < 128; ++row) {
        u64 tt[8];
        #pragma unroll
        for (int q = 0; q < 4; ++q) {
            ulonglong2 v = *(const ulonglong2*)(ts + row * R + q * 4);
            tt[2 * q]     = v.x;
            tt[2 * q + 1] = v.y;
        }
        float res[4];
        #pragma unroll
        for (int j = 0; j < 4; ++j) {
            u64 a = 0ULL;
            #pragma unroll
            for (int p = 0; p < 8; ++p)
                a = fma2(bb[j][p], tt[p], a);
            res[j] = hsum2(a);
        }
        *(float4*)(out + (rowBase + row) * (long)D + ob) =
            make_float4(res[0], res[1], res[2], res[3]);
    }
}

extern "C" void kernel_launch(void* const* d_in, const int* in_sizes, int n_in,
                              void* d_out, int out_size) {
    const float* x = (const float*)d_in[0];   // [16384, 4096]
    const float* A = (const float*)d_in[1];   // [16, 4096]
    const float* B = (const float*)d_in[2];   // [4096, 16]
    float* out = (float*)d_out;               // [16384, 4096]

    dim3 g1(ROWS_TOTAL / 64, 2);
    lora_stage1<<<g1, 256>>>(x, A);
    dim3 g2(D / 1024, ROWS_TOTAL / 128);
    lora_stage2<<<g2, 256>>>(B, out);
}

// round 15
// speedup vs baseline: 1.6392x; 1.6392x over previous
#include <cuda_runtime.h>
#include <cstdint>

// LoRA linear via rank-16 factor, FUSED single kernel:
//   per 64-row block:  t = x_tile @ A^T  (R6 pipeline, t -> smem)
//                      out_tile = t @ B^T (R6 stage2 form, 4 col-strips)
//   t never touches DRAM; one launch; ncu captures the whole thing.

#define D 4096
#define R 16
#define ROWS_TOTAL 16384
#define KC 32
#define NCH (D / KC)        // 128 chunks
#define ADS 18              // ad row stride in u64
#define AD_STAGE (16 * ADS)

typedef unsigned long long u64;

__device__ __forceinline__ u64 fma2(u64 a, u64 b, u64 c) {
    u64 d; asm("fma.rn.f32x2 %0,%1,%2,%3;" : "=l"(d) : "l"(a), "l"(b), "l"(c)); return d;
}
__device__ __forceinline__ u64 pack2(float lo, float hi) {
    u64 d; asm("mov.b64 %0,{%1,%2};" : "=l"(d) : "f"(lo), "f"(hi)); return d;
}
__device__ __forceinline__ float hsum2(u64 v) {
    float lo, hi; asm("mov.b64 {%0,%1},%2;" : "=f"(lo), "=f"(hi) : "l"(v)); return lo + hi;
}
__device__ __forceinline__ void cp16(uint32_t d, const void* s) {
    asm volatile("cp.async.cg.shared.global [%0],[%1],16;" :: "r"(d), "l"(s));
}
__device__ __forceinline__ void cpcommit() { asm volatile("cp.async.commit_group;"); }
__device__ __forceinline__ void cpwait2()  { asm volatile("cp.async.wait_group 2;"); }

// Block 256 thr / 8 warps, 64 rows, grid 256, 2 CTAs/SM.
// Phase 1 (R6-proven): lane owns rows (2l, 2l+1); warp w owns k=w*4..w*4+3;
// f32x2 over (k-even,k-odd); broadcast-A ad table; 4-stage cp.async ring,
// ONE __syncthreads per chunk, wait_group 2 (3 chunks in flight).
// Phase 2 (R6-proven): 4 strips x 1024 cols; thread owns 4 cols; bb in regs;
// t broadcast from smem; STG.128.
__global__ void __launch_bounds__(256, 2)
lora_fused(const float* __restrict__ x, const float* __restrict__ A,
           const float* __restrict__ B, float* __restrict__ out)
{
    __shared__ __align__(16) unsigned char sm[42 * 1024];
    float* xs = (float*)sm;                  // [4][64 rows][32 k]  32 KB
    u64*   ad = (u64*)(sm + 32768);          // [4][16][ADS]        9.2 KB
    float* redf = (float*)sm;                // [8][64*17] overlay  34.8 KB
    __shared__ float ts[64 * R];             // 4 KB t tile

    const int tid  = threadIdx.x;
    const int w    = tid >> 5;
    const int lane = tid & 31;
    const long rowBase = (long)blockIdx.x * 64;

    // x cp.async role: row = tid>>2, seg = tid&3 (8 floats = 2 slots)
    const int trow = tid >> 2, tseg = tid & 3;
    const int tsw  = (trow >> 1) & 7;
    const int tph0 = (2 * tseg)     ^ tsw;
    const int tph1 = (2 * tseg + 1) ^ tsw;
    const float* xsrc = x + (rowBase + trow) * D;
    const uint32_t xs_sh = (uint32_t)__cvta_generic_to_shared(sm);

    // A role: r = tid>>4, kp = tid&15 (coalesced float2 per r-row)
    const int ar = tid >> 4, akp = tid & 15;
    const float* asrc = A + (long)ar * D + 2 * akp;

    // compute-role constants
    const int r0  = 2 * lane;
    const int pcs = (w ^ (lane & 7)) * 4;

    u64 acc0[16], acc1[16];
    #pragma unroll
    for (int r = 0; r < 16; ++r) { acc0[r] = 0ULL; acc1[r] = 0ULL; }

    // ---- prologue: x chunks 0..2 in flight, A(0..1) staged, A(2) in regs ----
    #pragma unroll
    for (int cc = 0; cc < 3; ++cc) {
        const float* xp = xsrc + cc * KC + tseg * 8;
        cp16(xs_sh + (uint32_t)(cc * 2048 + trow * 32 + tph0 * 4) * 4u, xp);
        cp16(xs_sh + (uint32_t)(cc * 2048 + trow * 32 + tph1 * 4) * 4u, xp + 4);
        cpcommit();
    }
    {
        float2 t0 = *(const float2*)(asrc);
        float2 t1 = *(const float2*)(asrc + KC);
        ad[0 * AD_STAGE + akp * ADS + ar] = pack2(t0.x, t0.y);
        ad[1 * AD_STAGE + akp * ADS + ar] = pack2(t1.x, t1.y);
    }
    float2 apf = *(const float2*)(asrc + 2 * KC);

    #pragma unroll 4
    for (int c = 0; c < NCH; ++c) {
        const int s = c & 3;
        cpwait2();           // chunk c landed (this thread's groups)
        __syncthreads();     // visible to all + compute(c-1) done

        if (c + 3 < NCH) {
            const float* xp = xsrc + (c + 3) * KC + tseg * 8;
            const uint32_t base = (uint32_t)(((c + 3) & 3) * 2048 + trow * 32);
            cp16(xs_sh + (base + tph0 * 4) * 4u, xp);
            cp16(xs_sh + (base + tph1 * 4) * 4u, xp + 4);
        }
        cpcommit();          // always: group count tracks chunk count

        if (c + 2 < NCH)
            ad[((c + 2) & 3) * AD_STAGE + akp * ADS + ar] = pack2(apf.x, apf.y);
        if (c + 3 < NCH)
            apf = *(const float2*)(asrc + (c + 3) * KC);

        // ---- compute chunk c: k = w*4..w*4+3 (k-pairs 2w, 2w+1) ----
        const float* xb = xs + s * 2048;
        ulonglong2 xa = *(const ulonglong2*)(xb + r0 * 32 + pcs);
        ulonglong2 ya = *(const ulonglong2*)(xb + (r0 + 1) * 32 + pcs);
        #pragma unroll
        for (int kp2 = 0; kp2 < 2; ++kp2) {
            const u64 xv = kp2 ? xa.y : xa.x;
            const u64 yv = kp2 ? ya.y : ya.x;
            const u64* adk = ad + s * AD_STAGE + (w * 2 + kp2) * ADS;
            #pragma unroll
            for (int rr = 0; rr < 8; ++rr) {
                ulonglong2 av = *(const ulonglong2*)(adk + 2 * rr);  // broadcast
                acc0[2 * rr]     = fma2(xv, av.x, acc0[2 * rr]);
                acc0[2 * rr + 1] = fma2(xv, av.y, acc0[2 * rr + 1]);
                acc1[2 * rr]     = fma2(yv, av.x, acc1[2 * rr]);
                acc1[2 * rr + 1] = fma2(yv, av.y, acc1[2 * rr + 1]);
            }
        }
    }

    // ---- cross-warp reduction into smem t tile ----
    __syncthreads();   // done with xs/ad -> overlay redf
    #pragma unroll
    for (int r = 0; r < 16; ++r) {
        redf[w * 1088 + (r0)     * 17 + r] = hsum2(acc0[r]);
        redf[w * 1088 + (r0 + 1) * 17 + r] = hsum2(acc1[r]);
    }
    __syncthreads();

    #pragma unroll
    for (int i = 0; i < 4; ++i) {
        const int e = tid + 256 * i;          // 0..1023
        const int row = e >> 4, r = e & 15;
        float sum = 0.f;
        #pragma unroll
        for (int ww = 0; ww < 8; ++ww)
            sum += redf[ww * 1088 + row * 17 + r];
        ts[row * R + r] = sum;
    }
    __syncthreads();   // t tile complete, visible to all

    // ---------------- Phase 2: out_tile = t @ B^T ----------------
    #pragma unroll 1
    for (int strip = 0; strip < 4; ++strip) {
        const int ob = strip * 1024 + tid * 4;
        u64 bb[4][8];
        #pragma unroll
        for (int j = 0; j < 4; ++j) {
            const float* bp = B + (long)(ob + j) * R;
            ulonglong2 v0 = *(const ulonglong2*)(bp);
            ulonglong2 v1 = *(const ulonglong2*)(bp + 4);
            ulonglong2 v2 = *(const ulonglong2*)(bp + 8);
            ulonglong2 v3 = *(const ulonglong2*)(bp + 12);
            bb[j][0] = v0.x; bb[j][1] = v0.y;
            bb[j][2] = v1.x; bb[j][3] = v1.y;
            bb[j][4] = v2.x; bb[j][5] = v2.y;
            bb[j][6] = v3.x; bb[j][7] = v3.y;
        }

        for (int row = 0; row < 64; ++row) {
            u64 tt[8];
            #pragma unroll
            for (int q = 0; q < 4; ++q) {
                ulonglong2 v = *(const ulonglong2*)(ts + row * R + q * 4);
                tt[2 * q]     = v.x;
                tt[2 * q + 1] = v.y;
            }
            float res[4];
            #pragma unroll
            for (int j = 0; j < 4; ++j) {
                u64 a = 0ULL;
                #pragma unroll
                for (int p = 0; p < 8; ++p)
                    a = fma2(bb[j][p], tt[p], a);
                res[j] = hsum2(a);
            }
            *(float4*)(out + (rowBase + row) * (long)D + ob) =
                make_float4(res[0], res[1], res[2], res[3]);
        }
    }
}

extern "C" void kernel_launch(void* const* d_in, const int* in_sizes, int n_in,
                              void* d_out, int out_size) {
    const float* x = (const float*)d_in[0];   // [16384, 4096]
    const float* A = (const float*)d_in[1];   // [16, 4096]
    const float* B = (const float*)d_in[2];   // [4096, 16]
    float* out = (float*)d_out;               // [16384, 4096]

    lora_fused<<<ROWS_TOTAL / 64, 256>>>(x, A, B, out);
}